// round 6
// baseline (speedup 1.0000x reference)
#include <cuda_runtime.h>
#include <cuda_bf16.h>
#include <math.h>

// Problem constants
#define NN 20000
#define EE 200000
#define UU 32
#define RR 64
#define NTYPES 95
#define PI_F 3.14159265358979323846f

#define EDGE_TILE    64
#define EDGE_TILES   (EE / EDGE_TILE)   // 3125 tiles of 64 edges
#define EDGE_BLOCKS  444                // grid-stride

typedef unsigned long long ull;

// packed f32x2 FMA: d.lo += a.lo*b.lo ; d.hi += a.hi*b.hi
#define FMA2(d, a, b) \
    asm("fma.rn.f32x2 %0, %1, %2, %0;" : "+l"(d) : "l"(a), "l"(b))
#define UNPK2(lo, hi, v) \
    asm("mov.b64 {%0, %1}, %2;" : "=f"(lo), "=f"(hi) : "l"(v))

// ---------------------------------------------------------------------------
// Device scratch (static allocations only — no cudaMalloc allowed)
// ---------------------------------------------------------------------------
__device__ int    g_counts[NN];
__device__ int    g_offsets[NN + 1];
__device__ int    g_cursor[NN];
__device__ int    g_pos[EE];          // edge e -> CSR slot p
__device__ int    g_stype[EE];        // per CSR slot: node_type[src[e]]
__device__ float4 g_v4[EE];           // per CSR slot: normalized v (xyz) + cutoff C (w)
__device__ float  g_msg[(size_t)EE * 96]; // per CSR slot: W1[32] W2[32] W3[32]
__device__ float  g_Ylo[NTYPES * 32]; // per type: Z(type) @ Wemb2[0:32]
__device__ float  g_Yhi[NTYPES * 32]; // per type: Z(type) @ Wemb2[32:64]

// ---------------------------------------------------------------------------
// CSR build + per-type Zij precompute
// ---------------------------------------------------------------------------
__global__ void k_zero() {
    int i = blockIdx.x * blockDim.x + threadIdx.x;
    if (i < NN) g_counts[i] = 0;
}

__global__ void k_hist(const int* __restrict__ dst) {
    int e = blockIdx.x * blockDim.x + threadIdx.x;
    if (e < EE) atomicAdd(&g_counts[dst[e]], 1);
}

// single-block exclusive scan over NN counts -> offsets (+ cursor copy)
__global__ void k_scan() {
    __shared__ int sh[32];
    __shared__ int s_carry;
    int t = threadIdx.x;
    int lane = t & 31, wid = t >> 5;
    if (t == 0) s_carry = 0;
    __syncthreads();
    for (int base = 0; base < NN; base += 1024) {
        int i = base + t;
        int v = (i < NN) ? g_counts[i] : 0;
        int x = v;
        #pragma unroll
        for (int o = 1; o < 32; o <<= 1) {
            int y = __shfl_up_sync(0xFFFFFFFFu, x, o);
            if (lane >= o) x += y;
        }
        if (lane == 31) sh[wid] = x;
        __syncthreads();
        if (wid == 0) {
            int y = sh[lane];
            #pragma unroll
            for (int o = 1; o < 32; o <<= 1) {
                int z = __shfl_up_sync(0xFFFFFFFFu, y, o);
                if (lane >= o) y += z;
            }
            sh[lane] = y;
        }
        __syncthreads();
        int warpoff = (wid > 0) ? sh[wid - 1] : 0;
        int incl = x + warpoff + s_carry;
        if (i < NN) {
            g_offsets[i] = incl - v;
            g_cursor[i]  = incl - v;
        }
        __syncthreads();
        if (t == 1023) s_carry = incl;
        __syncthreads();
    }
    if (t == 0) g_offsets[NN] = s_carry;
}

// per-type Y tables: Y{lo,hi}[ty][u] = sum_k emb[ty][k] * Wemb2[{k, 32+k}][u]
__global__ void k_typeY(const float* __restrict__ emb,
                        const float* __restrict__ Wemb2) {
    int ty = blockIdx.x, u = threadIdx.x;
    float lo = 0.0f, hi = 0.0f;
    #pragma unroll 8
    for (int k = 0; k < 32; k++) {
        float z = __ldg(&emb[ty * 32 + k]);
        lo += z * __ldg(&Wemb2[k * 32 + u]);
        hi += z * __ldg(&Wemb2[(32 + k) * 32 + u]);
    }
    g_Ylo[ty * 32 + u] = lo;
    g_Yhi[ty * 32 + u] = hi;
}

__global__ void k_scatter(const int* __restrict__ dst,
                          const int* __restrict__ src,
                          const int* __restrict__ ntype,
                          const float* __restrict__ bdist,
                          const float* __restrict__ bvec) {
    int e = blockIdx.x * blockDim.x + threadIdx.x;
    if (e >= EE) return;
    int p = atomicAdd(&g_cursor[dst[e]], 1);
    g_pos[e] = p;
    g_stype[p] = __ldg(&ntype[__ldg(&src[e])]);
    float vx = bvec[3 * e + 0];
    float vy = bvec[3 * e + 1];
    float vz = bvec[3 * e + 2];
    float inv = rsqrtf(vx * vx + vy * vy + vz * vz);
    float d = bdist[e];
    float C = (d <= 5.0f) ? 0.5f * (cosf((PI_F / 5.0f) * d) + 1.0f) : 0.0f;
    g_v4[p] = make_float4(vx * inv, vy * inv, vz * inv, C);
}

// ---------------------------------------------------------------------------
// Edge kernel: fused [E,64]x[64,128] GEMM (Wd1|Wd2|Wd3|Wemb3), k-split packed
// f32x2 FMAs. Grid-stride persistent: weights staged into smem ONCE per block;
// 64-edge tiles looped. 256 threads; warp w -> edges 8w..8w+7; lane u = channel.
//
// Static smem (exactly 48 KB):
//   pWa : ulonglong2[32*32]  16 KB  {Wd1 k-pair, Wd2 k-pair} per (kp,u)
//   pWb : ulonglong2[32*32]  16 KB  {Wd3 k-pair, Wemb3 k-pair}
//   sEA : float[64*64]       16 KB  edge_attr tile
// ---------------------------------------------------------------------------
__global__ __launch_bounds__(256, 2) void k_edge(
    const float* __restrict__ ea,
    const float* __restrict__ Wd1, const float* __restrict__ Wd2,
    const float* __restrict__ Wd3, const float* __restrict__ Wemb3,
    const float* __restrict__ bd1, const float* __restrict__ bd2,
    const float* __restrict__ bd3, const float* __restrict__ bemb3,
    float* __restrict__ out_ef)
{
    __shared__ __align__(16) char smem[49152];
    ulonglong2* pWa = (ulonglong2*)(smem);               // 16 KB @ 0
    ulonglong2* pWb = (ulonglong2*)(smem + 16384);       // 16 KB
    float*      sEA = (float*)     (smem + 32768);       // 16 KB

    int t = threadIdx.x;
    int u = t & 31, w = t >> 5;
    int e0 = w * 8;

    // ---- stage weights once (k-pair packed) ----
    for (int i = t; i < 1024; i += 256) {
        int kp = i >> 5, uu = i & 31;
        float* pa = (float*)&pWa[i];
        pa[0] = Wd1[(2 * kp) * 32 + uu];
        pa[1] = Wd1[(2 * kp + 1) * 32 + uu];
        pa[2] = Wd2[(2 * kp) * 32 + uu];
        pa[3] = Wd2[(2 * kp + 1) * 32 + uu];
        float* pb = (float*)&pWb[i];
        pb[0] = Wd3[(2 * kp) * 32 + uu];
        pb[1] = Wd3[(2 * kp + 1) * 32 + uu];
        pb[2] = Wemb3[(2 * kp) * 32 + uu];
        pb[3] = Wemb3[(2 * kp + 1) * 32 + uu];
    }

    float b1 = __ldg(&bd1[u]), b2 = __ldg(&bd2[u]);
    float b3 = __ldg(&bd3[u]), be = __ldg(&bemb3[u]);

    for (int tile = blockIdx.x; tile < EDGE_TILES; tile += EDGE_BLOCKS) {
        int ebase = tile * EDGE_TILE;
        __syncthreads();   // WAR: previous tile consumed (covers weight staging on iter 0)

        // stage edge_attr tile [64,64]
        {
            const float4* ea4 = (const float4*)(ea + (size_t)ebase * 64);
            float4* sEA4 = (float4*)sEA;
            for (int i = t; i < 1024; i += 256) sEA4[i] = __ldg(&ea4[i]);
        }
        __syncthreads();

        // ---- main GEMM: k-split f32x2, kp processed in pairs (float4 ea) ----
        ull a0[8], a1[8], a2[8], a3[8];
        #pragma unroll
        for (int i = 0; i < 8; i++) { a0[i] = 0; a1[i] = 0; a2[i] = 0; a3[i] = 0; }

        #pragma unroll 2
        for (int kp2 = 0; kp2 < 16; kp2++) {
            ulonglong2 wa0 = pWa[(2 * kp2) * 32 + u];
            ulonglong2 wb0 = pWb[(2 * kp2) * 32 + u];
            ulonglong2 wa1 = pWa[(2 * kp2 + 1) * 32 + u];
            ulonglong2 wb1 = pWb[(2 * kp2 + 1) * 32 + u];
            #pragma unroll
            for (int i = 0; i < 8; i++) {
                ulonglong2 x2 = *(const ulonglong2*)&sEA[(e0 + i) * 64 + 4 * kp2];
                FMA2(a0[i], x2.x, wa0.x);
                FMA2(a1[i], x2.x, wa0.y);
                FMA2(a2[i], x2.x, wb0.x);
                FMA2(a3[i], x2.x, wb0.y);
                FMA2(a0[i], x2.y, wa1.x);
                FMA2(a1[i], x2.y, wa1.y);
                FMA2(a2[i], x2.y, wb1.x);
                FMA2(a3[i], x2.y, wb1.y);
            }
        }

        // ---- epilogue: horizontal add, bias, cutoff, store ----
        #pragma unroll
        for (int i = 0; i < 8; i++) {
            float lo, hi;
            UNPK2(lo, hi, a0[i]); float r0 = lo + hi;
            UNPK2(lo, hi, a1[i]); float r1 = lo + hi;
            UNPK2(lo, hi, a2[i]); float r2 = lo + hi;
            UNPK2(lo, hi, a3[i]); float r3 = lo + hi;

            int e = ebase + e0 + i;
            int p = __ldg(&g_pos[e]);
            float C = g_v4[p].w;
            float* m = &g_msg[(size_t)p * 96];
            m[u]      = (r0 + b1) * C;
            m[32 + u] = (r1 + b2) * C;
            m[64 + u] = (r2 + b3) * C;
            out_ef[(size_t)e * 32 + u] = r3 + be;
        }
    }
}

// ---------------------------------------------------------------------------
// Node kernel: warp per node, lane u = channel. Gathers CSR messages, builds
// the 10 sufficient statistics in registers, then LN + MLP + Wt-mixing + X.
// block = 512 (16 nodes). Static smem = 44 KB.
// ---------------------------------------------------------------------------
__global__ __launch_bounds__(512) void k_node(
    const int*   __restrict__ ntype,
    const float* __restrict__ bemb2,
    const float* __restrict__ Wt0, const float* __restrict__ Wt1,
    const float* __restrict__ Wt2,
    const float* __restrict__ Ws1, const float* __restrict__ bs1,
    const float* __restrict__ Ws2, const float* __restrict__ bs2,
    const float* __restrict__ lng, const float* __restrict__ lnb,
    float* __restrict__ outX)
{
    __shared__ float sWt[3][32 * 32];   // 12 KB
    __shared__ float sWs1[32 * 64];     //  8 KB
    __shared__ float sWs2[64 * 96];     // 24 KB

    int t = threadIdx.x;
    for (int i = t; i < 1024; i += 512) {
        sWt[0][i] = __ldg(&Wt0[i]); sWt[1][i] = __ldg(&Wt1[i]);
        sWt[2][i] = __ldg(&Wt2[i]);
    }
    for (int i = t; i < 2048; i += 512) sWs1[i] = __ldg(&Ws1[i]);
    for (int i = t; i < 6144; i += 512) sWs2[i] = __ldg(&Ws2[i]);
    __syncthreads();

    const unsigned FULL = 0xFFFFFFFFu;
    int wlocal = t >> 5, u = t & 31;
    int n = blockIdx.x * 16 + wlocal;
    if (n >= NN) return;

    // Z[dst] contribution (per-type table) + bias
    float zc = __ldg(&g_Yhi[__ldg(&ntype[n]) * 32 + u]) + __ldg(&bemb2[u]);

    // 10 sufficient statistics per channel
    float sI = 0, ax = 0, ay = 0, az = 0;
    float sxx = 0, syy = 0, szz = 0, sxy = 0, sxz = 0, syz = 0;

    int pb = g_offsets[n], pe = g_offsets[n + 1];
    #pragma unroll 4
    for (int p = pb; p < pe; p++) {
        const float* m = &g_msg[(size_t)p * 96];
        float w1 = m[u], w2 = m[32 + u], w3 = m[64 + u];
        int   st = __ldg(&g_stype[p]);
        float zl = __ldg(&g_Ylo[st * 32 + u]);
        float4 v = g_v4[p];
        float Zij = zc + zl;
        float fI = Zij * w1, fA = Zij * w2, fS = Zij * w3;
        sI  += fI;
        ax  += fA * v.x; ay += fA * v.y; az += fA * v.z;
        sxx += fS * (v.x * v.x - (1.0f / 3.0f));
        syy += fS * (v.y * v.y - (1.0f / 3.0f));
        szz += fS * (v.z * v.z - (1.0f / 3.0f));
        sxy += fS * v.x * v.y;
        sxz += fS * v.x * v.z;
        syz += fS * v.y * v.z;
    }

    // tensor_norm: ||Ie+Ae+Se||_F^2 (skew/sym cross terms cancel pairwise)
    float d0 = sI + sxx, d1 = sI + syy, d2 = sI + szz;
    float nrm = d0 * d0 + d1 * d1 + d2 * d2
              + 2.0f * (sxy * sxy + sxz * sxz + syz * syz
                        + ax * ax + ay * ay + az * az);

    // LayerNorm over the 32 channels (warp reduction)
    float s = nrm;
    #pragma unroll
    for (int o = 16; o; o >>= 1) s += __shfl_xor_sync(FULL, s, o);
    float mu = s * (1.0f / 32.0f);
    float dd = nrm - mu;
    float s2 = dd * dd;
    #pragma unroll
    for (int o = 16; o; o >>= 1) s2 += __shfl_xor_sync(FULL, s2, o);
    float var = s2 * (1.0f / 32.0f);
    float nh = dd * rsqrtf(var + 1e-5f) * __ldg(&lng[u]) + __ldg(&lnb[u]);

    // MLP: 32 -> 64 (silu) -> 96 (silu)
    float h1a = __ldg(&bs1[u]), h1b = __ldg(&bs1[u + 32]);
    #pragma unroll
    for (int k = 0; k < 32; k++) {
        float x = __shfl_sync(FULL, nh, k);
        h1a += x * sWs1[k * 64 + u];
        h1b += x * sWs1[k * 64 + 32 + u];
    }
    h1a = h1a / (1.0f + expf(-h1a));
    h1b = h1b / (1.0f + expf(-h1b));

    float o0 = __ldg(&bs2[3 * u]), o1 = __ldg(&bs2[3 * u + 1]);
    float o2 = __ldg(&bs2[3 * u + 2]);
    #pragma unroll
    for (int k = 0; k < 32; k++) {
        float x = __shfl_sync(FULL, h1a, k);
        o0 += x * sWs2[k * 96 + 3 * u];
        o1 += x * sWs2[k * 96 + 3 * u + 1];
        o2 += x * sWs2[k * 96 + 3 * u + 2];
    }
    #pragma unroll
    for (int k = 0; k < 32; k++) {
        float x = __shfl_sync(FULL, h1b, k);
        o0 += x * sWs2[(32 + k) * 96 + 3 * u];
        o1 += x * sWs2[(32 + k) * 96 + 3 * u + 1];
        o2 += x * sWs2[(32 + k) * 96 + 3 * u + 2];
    }
    float n0 = o0 / (1.0f + expf(-o0));
    float n1 = o1 / (1.0f + expf(-o1));
    float n2 = o2 / (1.0f + expf(-o2));

    // Channel mixing acts linearly on the sufficient statistics
    float ip = 0, axp = 0, ayp = 0, azp = 0;
    float pxx = 0, pyy = 0, pzz = 0, pxy = 0, pxz = 0, pyz = 0;
    #pragma unroll
    for (int k = 0; k < 32; k++) {
        float w0 = sWt[0][k * 32 + u];
        float w1 = sWt[1][k * 32 + u];
        float w2 = sWt[2][k * 32 + u];
        ip  += __shfl_sync(FULL, sI,  k) * w0;
        axp += __shfl_sync(FULL, ax,  k) * w1;
        ayp += __shfl_sync(FULL, ay,  k) * w1;
        azp += __shfl_sync(FULL, az,  k) * w1;
        pxx += __shfl_sync(FULL, sxx, k) * w2;
        pyy += __shfl_sync(FULL, syy, k) * w2;
        pzz += __shfl_sync(FULL, szz, k) * w2;
        pxy += __shfl_sync(FULL, sxy, k) * w2;
        pxz += __shfl_sync(FULL, sxz, k) * w2;
        pyz += __shfl_sync(FULL, syz, k) * w2;
    }

    // X[n][u][3][3]:  n0*diag(ip) + n1*skew(a') + n2*S(s')
    float* X = &outX[(size_t)n * 288 + u * 9];
    X[0] =  n0 * ip  + n2 * pxx;
    X[1] = -n1 * azp + n2 * pxy;
    X[2] =  n1 * ayp + n2 * pxz;
    X[3] =  n1 * azp + n2 * pxy;
    X[4] =  n0 * ip  + n2 * pyy;
    X[5] = -n1 * axp + n2 * pyz;
    X[6] = -n1 * ayp + n2 * pxz;
    X[7] =  n1 * axp + n2 * pyz;
    X[8] =  n0 * ip  + n2 * pzz;
}

// ---------------------------------------------------------------------------
// Launch
// ---------------------------------------------------------------------------
extern "C" void kernel_launch(void* const* d_in, const int* in_sizes, int n_in,
                              void* d_out, int out_size)
{
    (void)in_sizes; (void)n_in; (void)out_size;
    const int*   node_type = (const int*)  d_in[0];
    const float* edge_attr = (const float*)d_in[1];
    const float* bond_dist = (const float*)d_in[2];
    const float* bond_vec  = (const float*)d_in[3];
    const int*   src       = (const int*)  d_in[4];
    const int*   dst       = (const int*)  d_in[5];
    const float* emb       = (const float*)d_in[6];
    const float* Wd1   = (const float*)d_in[7];
    const float* bd1   = (const float*)d_in[8];
    const float* Wd2   = (const float*)d_in[9];
    const float* bd2   = (const float*)d_in[10];
    const float* Wd3   = (const float*)d_in[11];
    const float* bd3   = (const float*)d_in[12];
    const float* Wemb2 = (const float*)d_in[13];
    const float* bemb2 = (const float*)d_in[14];
    const float* Wemb3 = (const float*)d_in[15];
    const float* bemb3 = (const float*)d_in[16];
    const float* Wt0   = (const float*)d_in[17];
    const float* Wt1   = (const float*)d_in[18];
    const float* Wt2   = (const float*)d_in[19];
    const float* Ws1   = (const float*)d_in[20];
    const float* bs1   = (const float*)d_in[21];
    const float* Ws2   = (const float*)d_in[22];
    const float* bs2   = (const float*)d_in[23];
    const float* lng   = (const float*)d_in[24];
    const float* lnb   = (const float*)d_in[25];

    float* outX  = (float*)d_out;
    float* outEF = outX + (size_t)NN * 288;   // X first, then edge_feat

    k_zero   <<<(NN + 255) / 256, 256>>>();
    k_hist   <<<(EE + 255) / 256, 256>>>(dst);
    k_typeY  <<<NTYPES, 32>>>(emb, Wemb2);
    k_scan   <<<1, 1024>>>();
    k_scatter<<<(EE + 255) / 256, 256>>>(dst, src, node_type, bond_dist, bond_vec);
    k_edge   <<<EDGE_BLOCKS, 256>>>(edge_attr,
                                    Wd1, Wd2, Wd3, Wemb3,
                                    bd1, bd2, bd3, bemb3, outEF);
    k_node   <<<(NN + 15) / 16, 512>>>(node_type, bemb2,
                                       Wt0, Wt1, Wt2, Ws1, bs1, Ws2, bs2,
                                       lng, lnb, outX);
}

// round 17
// speedup vs baseline: 1.1851x; 1.1851x over previous
#include <cuda_runtime.h>
#include <cuda_bf16.h>
#include <math.h>

// Problem constants
#define NN 20000
#define EE 200000
#define UU 32
#define RR 64
#define NTYPES 95
#define PI_F 3.14159265358979323846f

#define EDGE_TILE    64
#define EDGE_TILES   (EE / EDGE_TILE)   // 3125 tiles of 64 edges
#define EDGE_BLOCKS  296                // EXACTLY 2 resident blocks/SM (reg-limited)

typedef unsigned long long ull;

// packed f32x2 FMA: d.lo += a.lo*b.lo ; d.hi += a.hi*b.hi
#define FMA2(d, a, b) \
    asm("fma.rn.f32x2 %0, %1, %2, %0;" : "+l"(d) : "l"(a), "l"(b))
#define UNPK2(lo, hi, v) \
    asm("mov.b64 {%0, %1}, %2;" : "=f"(lo), "=f"(hi) : "l"(v))

// ---------------------------------------------------------------------------
// Device scratch (static allocations only — no cudaMalloc allowed)
// NOTE: 16B alignment is REQUIRED on the int arrays touched with int4.
// ---------------------------------------------------------------------------
__device__ __align__(16) int    g_counts[NN];
__device__ __align__(16) int    g_offsets[NN + 4];  // padded, int4-stored
__device__ __align__(16) int    g_cursor[NN];
__device__ int    g_eid[EE];          // CSR slot p -> edge e
__device__ int    g_stype[EE];        // CSR slot p -> node_type[src[e]]
__device__ float4 g_v4[EE];           // CSR slot p -> normalized bond_vec
__device__ float  g_msg[(size_t)EE * 96]; // EDGE e -> W1[32] W2[32] W3[32]
__device__ float  g_Ylo[NTYPES * 32]; // per type: Z(type) @ Wemb2[0:32]
__device__ float  g_Yhi[NTYPES * 32]; // per type: Z(type) @ Wemb2[32:64]

// ---------------------------------------------------------------------------
// init: zero counts (blocks 0..78) + per-type Y tables (blocks 79..90)
// ---------------------------------------------------------------------------
__global__ void k_init(const float* __restrict__ emb,
                       const float* __restrict__ Wemb2) {
    int b = blockIdx.x;
    if (b < 79) {
        int i = b * 256 + threadIdx.x;
        if (i < NN) g_counts[i] = 0;
    } else {
        int idx = (b - 79) * 256 + threadIdx.x;   // 0 .. 3071 (need 3040)
        if (idx < NTYPES * 32) {
            int ty = idx >> 5, u = idx & 31;
            float lo = 0.0f, hi = 0.0f;
            #pragma unroll 8
            for (int k = 0; k < 32; k++) {
                float z = __ldg(&emb[ty * 32 + k]);
                lo += z * __ldg(&Wemb2[k * 32 + u]);
                hi += z * __ldg(&Wemb2[(32 + k) * 32 + u]);
            }
            g_Ylo[ty * 32 + u] = lo;
            g_Yhi[ty * 32 + u] = hi;
        }
    }
}

__global__ void k_hist(const int* __restrict__ dst) {
    int e = blockIdx.x * blockDim.x + threadIdx.x;
    if (e < EE) atomicAdd(&g_counts[dst[e]], 1);
}

// single-block exclusive scan, int4-vectorized: 5000 int4 = 20000 ints,
// 5 iterations of 1024 threads.
__global__ void k_scan() {
    __shared__ int sh[32];
    __shared__ int s_carry;
    int t = threadIdx.x;
    int lane = t & 31, wid = t >> 5;
    if (t == 0) s_carry = 0;
    __syncthreads();
    const int4* c4 = (const int4*)g_counts;
    for (int base = 0; base < 5000; base += 1024) {
        int i4 = base + t;
        int4 c = (i4 < 5000) ? c4[i4] : make_int4(0, 0, 0, 0);
        int v = c.x + c.y + c.z + c.w;
        int x = v;
        #pragma unroll
        for (int o = 1; o < 32; o <<= 1) {
            int y = __shfl_up_sync(0xFFFFFFFFu, x, o);
            if (lane >= o) x += y;
        }
        if (lane == 31) sh[wid] = x;
        __syncthreads();
        if (wid == 0) {
            int y = sh[lane];
            #pragma unroll
            for (int o = 1; o < 32; o <<= 1) {
                int z = __shfl_up_sync(0xFFFFFFFFu, y, o);
                if (lane >= o) y += z;
            }
            sh[lane] = y;
        }
        __syncthreads();
        int warpoff = (wid > 0) ? sh[wid - 1] : 0;
        int incl = x + warpoff + s_carry;
        if (i4 < 5000) {
            int o0 = incl - v;
            int o1 = o0 + c.x, o2 = o1 + c.y, o3 = o2 + c.z;
            ((int4*)g_offsets)[i4] = make_int4(o0, o1, o2, o3);
            ((int4*)g_cursor)[i4]  = make_int4(o0, o1, o2, o3);
        }
        __syncthreads();
        if (t == 1023) s_carry = incl;
        __syncthreads();
    }
    if (t == 0) g_offsets[NN] = s_carry;
}

__global__ void k_scatter(const int* __restrict__ dst,
                          const int* __restrict__ src,
                          const int* __restrict__ ntype,
                          const float* __restrict__ bvec) {
    int e = blockIdx.x * blockDim.x + threadIdx.x;
    if (e >= EE) return;
    int p = atomicAdd(&g_cursor[dst[e]], 1);
    g_eid[p] = e;
    g_stype[p] = __ldg(&ntype[__ldg(&src[e])]);
    float vx = bvec[3 * e + 0];
    float vy = bvec[3 * e + 1];
    float vz = bvec[3 * e + 2];
    float inv = rsqrtf(vx * vx + vy * vy + vz * vz);
    g_v4[p] = make_float4(vx * inv, vy * inv, vz * inv, 0.0f);
}

// ---------------------------------------------------------------------------
// Edge kernel: fused [E,64]x[64,128] GEMM (Wd1|Wd2|Wd3|Wemb3), k-split packed
// f32x2 FMAs. Independent of the CSR chain: messages stored by EDGE id
// (contiguous, coalesced), cutoff C computed inline from bond_dist (MUFU cos).
// Grid-stride persistent, 296 blocks (exactly 2/SM). 256 threads;
// warp w -> edges 8w..8w+7; lane u = output channel.
//
// Static smem (exactly 48 KB):
//   pWa : ulonglong2[32*32]  16 KB  {Wd1 k-pair, Wd2 k-pair} per (kp,u)
//   pWb : ulonglong2[32*32]  16 KB  {Wd3 k-pair, Wemb3 k-pair}
//   sEA : float[64*64]       16 KB  edge_attr tile
// ---------------------------------------------------------------------------
__global__ __launch_bounds__(256, 2) void k_edge(
    const float* __restrict__ ea,
    const float* __restrict__ bdist,
    const float* __restrict__ Wd1, const float* __restrict__ Wd2,
    const float* __restrict__ Wd3, const float* __restrict__ Wemb3,
    const float* __restrict__ bd1, const float* __restrict__ bd2,
    const float* __restrict__ bd3, const float* __restrict__ bemb3,
    float* __restrict__ out_ef)
{
    __shared__ __align__(16) char smem[49152];
    ulonglong2* pWa = (ulonglong2*)(smem);               // 16 KB @ 0
    ulonglong2* pWb = (ulonglong2*)(smem + 16384);       // 16 KB
    float*      sEA = (float*)     (smem + 32768);       // 16 KB

    int t = threadIdx.x;
    int u = t & 31, w = t >> 5;
    int e0 = w * 8;

    // ---- stage weights once (k-pair packed) ----
    for (int i = t; i < 1024; i += 256) {
        int kp = i >> 5, uu = i & 31;
        float* pa = (float*)&pWa[i];
        pa[0] = Wd1[(2 * kp) * 32 + uu];
        pa[1] = Wd1[(2 * kp + 1) * 32 + uu];
        pa[2] = Wd2[(2 * kp) * 32 + uu];
        pa[3] = Wd2[(2 * kp + 1) * 32 + uu];
        float* pb = (float*)&pWb[i];
        pb[0] = Wd3[(2 * kp) * 32 + uu];
        pb[1] = Wd3[(2 * kp + 1) * 32 + uu];
        pb[2] = Wemb3[(2 * kp) * 32 + uu];
        pb[3] = Wemb3[(2 * kp + 1) * 32 + uu];
    }

    float b1 = __ldg(&bd1[u]), b2 = __ldg(&bd2[u]);
    float b3 = __ldg(&bd3[u]), be = __ldg(&bemb3[u]);

    for (int tile = blockIdx.x; tile < EDGE_TILES; tile += EDGE_BLOCKS) {
        int ebase = tile * EDGE_TILE;
        __syncthreads();   // WAR: previous tile consumed (covers weight staging on iter 0)

        // stage edge_attr tile [64,64]
        {
            const float4* ea4 = (const float4*)(ea + (size_t)ebase * 64);
            float4* sEA4 = (float4*)sEA;
            for (int i = t; i < 1024; i += 256) sEA4[i] = __ldg(&ea4[i]);
        }
        __syncthreads();

        // ---- main GEMM: k-split f32x2, kp processed in pairs (float4 ea) ----
        ull a0[8], a1[8], a2[8], a3[8];
        #pragma unroll
        for (int i = 0; i < 8; i++) { a0[i] = 0; a1[i] = 0; a2[i] = 0; a3[i] = 0; }

        #pragma unroll 2
        for (int kp2 = 0; kp2 < 16; kp2++) {
            ulonglong2 wa0 = pWa[(2 * kp2) * 32 + u];
            ulonglong2 wb0 = pWb[(2 * kp2) * 32 + u];
            ulonglong2 wa1 = pWa[(2 * kp2 + 1) * 32 + u];
            ulonglong2 wb1 = pWb[(2 * kp2 + 1) * 32 + u];
            #pragma unroll
            for (int i = 0; i < 8; i++) {
                ulonglong2 x2 = *(const ulonglong2*)&sEA[(e0 + i) * 64 + 4 * kp2];
                FMA2(a0[i], x2.x, wa0.x);
                FMA2(a1[i], x2.x, wa0.y);
                FMA2(a2[i], x2.x, wb0.x);
                FMA2(a3[i], x2.x, wb0.y);
                FMA2(a0[i], x2.y, wa1.x);
                FMA2(a1[i], x2.y, wa1.y);
                FMA2(a2[i], x2.y, wb1.x);
                FMA2(a3[i], x2.y, wb1.y);
            }
        }

        // ---- epilogue: horizontal add, bias, cutoff, coalesced store by e ----
        #pragma unroll
        for (int i = 0; i < 8; i++) {
            float lo, hi;
            UNPK2(lo, hi, a0[i]); float r0 = lo + hi;
            UNPK2(lo, hi, a1[i]); float r1 = lo + hi;
            UNPK2(lo, hi, a2[i]); float r2 = lo + hi;
            UNPK2(lo, hi, a3[i]); float r3 = lo + hi;

            int e = ebase + e0 + i;
            float d = __ldg(&bdist[e]);
            // __cosf: MUFU.COS, |err| ~ 2^-21 on [0, pi] — 3 orders below the
            // 1e-3 gate (measured kernel rel_err 4e-7 with scalar cosf).
            float C = (d <= 5.0f) ? 0.5f * (__cosf((PI_F / 5.0f) * d) + 1.0f) : 0.0f;
            float* m = &g_msg[(size_t)e * 96];
            m[u]      = (r0 + b1) * C;
            m[32 + u] = (r1 + b2) * C;
            m[64 + u] = (r2 + b3) * C;
            out_ef[(size_t)e * 32 + u] = r3 + be;
        }
    }
}

// ---------------------------------------------------------------------------
// Node kernel: warp per node, lane u = channel. Gathers messages via g_eid,
// builds the 10 sufficient statistics in registers, then LN + MLP + mixing.
// block = 512 (16 nodes). Static smem = 44 KB.
// ---------------------------------------------------------------------------
__global__ __launch_bounds__(512) void k_node(
    const int*   __restrict__ ntype,
    const float* __restrict__ bemb2,
    const float* __restrict__ Wt0, const float* __restrict__ Wt1,
    const float* __restrict__ Wt2,
    const float* __restrict__ Ws1, const float* __restrict__ bs1,
    const float* __restrict__ Ws2, const float* __restrict__ bs2,
    const float* __restrict__ lng, const float* __restrict__ lnb,
    float* __restrict__ outX)
{
    __shared__ float sWt[3][32 * 32];   // 12 KB
    __shared__ float sWs1[32 * 64];     //  8 KB
    __shared__ float sWs2[64 * 96];     // 24 KB

    int t = threadIdx.x;
    for (int i = t; i < 1024; i += 512) {
        sWt[0][i] = __ldg(&Wt0[i]); sWt[1][i] = __ldg(&Wt1[i]);
        sWt[2][i] = __ldg(&Wt2[i]);
    }
    for (int i = t; i < 2048; i += 512) sWs1[i] = __ldg(&Ws1[i]);
    for (int i = t; i < 6144; i += 512) sWs2[i] = __ldg(&Ws2[i]);
    __syncthreads();

    const unsigned FULL = 0xFFFFFFFFu;
    int wlocal = t >> 5, u = t & 31;
    int n = blockIdx.x * 16 + wlocal;
    if (n >= NN) return;

    // Z[dst] contribution (per-type table) + bias
    float zc = __ldg(&g_Yhi[__ldg(&ntype[n]) * 32 + u]) + __ldg(&bemb2[u]);

    // 10 sufficient statistics per channel
    float sI = 0, ax = 0, ay = 0, az = 0;
    float sxx = 0, syy = 0, szz = 0, sxy = 0, sxz = 0, syz = 0;

    int pb = g_offsets[n], pe = g_offsets[n + 1];
    #pragma unroll 4
    for (int p = pb; p < pe; p++) {
        int eid = __ldg(&g_eid[p]);
        const float* m = &g_msg[(size_t)eid * 96];
        float w1 = m[u], w2 = m[32 + u], w3 = m[64 + u];
        int   st = __ldg(&g_stype[p]);
        float zl = __ldg(&g_Ylo[st * 32 + u]);
        float4 v = g_v4[p];
        float Zij = zc + zl;
        float fI = Zij * w1, fA = Zij * w2, fS = Zij * w3;
        sI  += fI;
        ax  += fA * v.x; ay += fA * v.y; az += fA * v.z;
        sxx += fS * (v.x * v.x - (1.0f / 3.0f));
        syy += fS * (v.y * v.y - (1.0f / 3.0f));
        szz += fS * (v.z * v.z - (1.0f / 3.0f));
        sxy += fS * v.x * v.y;
        sxz += fS * v.x * v.z;
        syz += fS * v.y * v.z;
    }

    // tensor_norm: ||Ie+Ae+Se||_F^2 (skew/sym cross terms cancel pairwise)
    float d0 = sI + sxx, d1 = sI + syy, d2 = sI + szz;
    float nrm = d0 * d0 + d1 * d1 + d2 * d2
              + 2.0f * (sxy * sxy + sxz * sxz + syz * syz
                        + ax * ax + ay * ay + az * az);

    // LayerNorm over the 32 channels (warp reduction)
    float s = nrm;
    #pragma unroll
    for (int o = 16; o; o >>= 1) s += __shfl_xor_sync(FULL, s, o);
    float mu = s * (1.0f / 32.0f);
    float dd = nrm - mu;
    float s2 = dd * dd;
    #pragma unroll
    for (int o = 16; o; o >>= 1) s2 += __shfl_xor_sync(FULL, s2, o);
    float var = s2 * (1.0f / 32.0f);
    float nh = dd * rsqrtf(var + 1e-5f) * __ldg(&lng[u]) + __ldg(&lnb[u]);

    // MLP: 32 -> 64 (silu) -> 96 (silu)
    float h1a = __ldg(&bs1[u]), h1b = __ldg(&bs1[u + 32]);
    #pragma unroll
    for (int k = 0; k < 32; k++) {
        float x = __shfl_sync(FULL, nh, k);
        h1a += x * sWs1[k * 64 + u];
        h1b += x * sWs1[k * 64 + 32 + u];
    }
    h1a = h1a / (1.0f + expf(-h1a));
    h1b = h1b / (1.0f + expf(-h1b));

    float o0 = __ldg(&bs2[3 * u]), o1 = __ldg(&bs2[3 * u + 1]);
    float o2 = __ldg(&bs2[3 * u + 2]);
    #pragma unroll
    for (int k = 0; k < 32; k++) {
        float x = __shfl_sync(FULL, h1a, k);
        o0 += x * sWs2[k * 96 + 3 * u];
        o1 += x * sWs2[k * 96 + 3 * u + 1];
        o2 += x * sWs2[k * 96 + 3 * u + 2];
    }
    #pragma unroll
    for (int k = 0; k < 32; k++) {
        float x = __shfl_sync(FULL, h1b, k);
        o0 += x * sWs2[(32 + k) * 96 + 3 * u];
        o1 += x * sWs2[(32 + k) * 96 + 3 * u + 1];
        o2 += x * sWs2[(32 + k) * 96 + 3 * u + 2];
    }
    float n0 = o0 / (1.0f + expf(-o0));
    float n1 = o1 / (1.0f + expf(-o1));
    float n2 = o2 / (1.0f + expf(-o2));

    // Channel mixing acts linearly on the sufficient statistics
    float ip = 0, axp = 0, ayp = 0, azp = 0;
    float pxx = 0, pyy = 0, pzz = 0, pxy = 0, pxz = 0, pyz = 0;
    #pragma unroll
    for (int k = 0; k < 32; k++) {
        float w0 = sWt[0][k * 32 + u];
        float w1 = sWt[1][k * 32 + u];
        float w2 = sWt[2][k * 32 + u];
        ip  += __shfl_sync(FULL, sI,  k) * w0;
        axp += __shfl_sync(FULL, ax,  k) * w1;
        ayp += __shfl_sync(FULL, ay,  k) * w1;
        azp += __shfl_sync(FULL, az,  k) * w1;
        pxx += __shfl_sync(FULL, sxx, k) * w2;
        pyy += __shfl_sync(FULL, syy, k) * w2;
        pzz += __shfl_sync(FULL, szz, k) * w2;
        pxy += __shfl_sync(FULL, sxy, k) * w2;
        pxz += __shfl_sync(FULL, sxz, k) * w2;
        pyz += __shfl_sync(FULL, syz, k) * w2;
    }

    // X[n][u][3][3]:  n0*diag(ip) + n1*skew(a') + n2*S(s')
    float* X = &outX[(size_t)n * 288 + u * 9];
    X[0] =  n0 * ip  + n2 * pxx;
    X[1] = -n1 * azp + n2 * pxy;
    X[2] =  n1 * ayp + n2 * pxz;
    X[3] =  n1 * azp + n2 * pxy;
    X[4] =  n0 * ip  + n2 * pyy;
    X[5] = -n1 * axp + n2 * pyz;
    X[6] = -n1 * ayp + n2 * pxz;
    X[7] =  n1 * axp + n2 * pyz;
    X[8] =  n0 * ip  + n2 * pzz;
}

// ---------------------------------------------------------------------------
// Launch (k_edge deliberately 4th: ncu captures the 4th launch)
// ---------------------------------------------------------------------------
extern "C" void kernel_launch(void* const* d_in, const int* in_sizes, int n_in,
                              void* d_out, int out_size)
{
    (void)in_sizes; (void)n_in; (void)out_size;
    const int*   node_type = (const int*)  d_in[0];
    const float* edge_attr = (const float*)d_in[1];
    const float* bond_dist = (const float*)d_in[2];
    const float* bond_vec  = (const float*)d_in[3];
    const int*   src       = (const int*)  d_in[4];
    const int*   dst       = (const int*)  d_in[5];
    const float* emb       = (const float*)d_in[6];
    const float* Wd1   = (const float*)d_in[7];
    const float* bd1   = (const float*)d_in[8];
    const float* Wd2   = (const float*)d_in[9];
    const float* bd2   = (const float*)d_in[10];
    const float* Wd3   = (const float*)d_in[11];
    const float* bd3   = (const float*)d_in[12];
    const float* Wemb2 = (const float*)d_in[13];
    const float* bemb2 = (const float*)d_in[14];
    const float* Wemb3 = (const float*)d_in[15];
    const float* bemb3 = (const float*)d_in[16];
    const float* Wt0   = (const float*)d_in[17];
    const float* Wt1   = (const float*)d_in[18];
    const float* Wt2   = (const float*)d_in[19];
    const float* Ws1   = (const float*)d_in[20];
    const float* bs1   = (const float*)d_in[21];
    const float* Ws2   = (const float*)d_in[22];
    const float* bs2   = (const float*)d_in[23];
    const float* lng   = (const float*)d_in[24];
    const float* lnb   = (const float*)d_in[25];

    float* outX  = (float*)d_out;
    float* outEF = outX + (size_t)NN * 288;   // X first, then edge_feat

    k_init   <<<91, 256>>>(emb, Wemb2);                      // 1: zero + typeY
    k_hist   <<<(EE + 255) / 256, 256>>>(dst);               // 2
    k_scan   <<<1, 1024>>>();                                 // 3
    k_edge   <<<EDGE_BLOCKS, 256>>>(edge_attr, bond_dist,    // 4  <- profiled
                                    Wd1, Wd2, Wd3, Wemb3,
                                    bd1, bd2, bd3, bemb3, outEF);
    k_scatter<<<(EE + 255) / 256, 256>>>(dst, src, node_type, bond_vec); // 5
    k_node   <<<(NN + 15) / 16, 512>>>(node_type, bemb2,     // 6
                                       Wt0, Wt1, Wt2, Ws1, bs1, Ws2, bs2,
                                       lng, lnb, outX);
}